// round 6
// baseline (speedup 1.0000x reference)
#include <cuda_runtime.h>

#define N_REL   200
#define BATCH   16384
#define DIM     128
#define N_ENT   500000
#define TILE    8
#define NBLOCKS 296
#define THREADS 512
#define MAXT    16

// Scratch (static __device__ globals — no allocation allowed)
__device__ int          g_cnt[N_REL];          // zero at start; reset by last block
__device__ int          g_list[N_REL * BATCH];
__device__ float        g_part[NBLOCKS];
__device__ unsigned int g_done;                // zero-init; reset by last block

typedef unsigned long long ull;

// ---- packed f32x2 helpers (pos/neg bilinears share one issue slot) ----
__device__ __forceinline__ ull ffma2(ull a, ull b, ull c) {
    ull d;
    asm("fma.rn.f32x2 %0, %1, %2, %3;" : "=l"(d) : "l"(a), "l"(b), "l"(c));
    return d;
}
__device__ __forceinline__ ull mul2(ull a, ull b) {
    ull d;
    asm("mul.rn.f32x2 %0, %1, %2;" : "=l"(d) : "l"(a), "l"(b));
    return d;
}
__device__ __forceinline__ ull dup2(float x) {
    ull d; unsigned int xi = __float_as_uint(x);
    asm("mov.b64 %0, {%1, %2};" : "=l"(d) : "r"(xi), "r"(xi));
    return d;
}

// ---- cp.async helpers ----
__device__ __forceinline__ void cp4(void* dst, const void* src) {
    unsigned sa = (unsigned)__cvta_generic_to_shared(dst);
    asm volatile("cp.async.ca.shared.global [%0], [%1], 4;" :: "r"(sa), "l"(src));
}
__device__ __forceinline__ void cp_commit() {
    asm volatile("cp.async.commit_group;" ::: "memory");
}
__device__ __forceinline__ void cp_wait1() {
    asm volatile("cp.async.wait_group 1;" ::: "memory");
}
__device__ __forceinline__ void cp_wait0() {
    asm volatile("cp.async.wait_group 0;" ::: "memory");
}

// Detect int64-vs-int32 index dtype from first 32 elements.
__device__ __forceinline__ int detect_is64(const void* data) {
    const unsigned int* w = (const unsigned int*)data;
    unsigned int acc = 0;
    #pragma unroll
    for (int k = 0; k < 32; k++) acc |= w[2 * k + 1];
    return (acc == 0) ? 1 : 0;   // true int64 (<2^31) => odd words all zero
}

// Read data[elem] under either index dtype, with defensive clamping.
__device__ __forceinline__ int read_idx(const void* data, int elem, int is64, int limit) {
    long long v;
    if (is64) v = ((const long long*)data)[elem];
    else      v = ((const int*)data)[elem];
    if (v < 0) v = 0;
    if (v >= limit) v = limit - 1;
    return (int)v;
}

// Bucket batch elements by relation id (g_cnt is zero on entry:
// zero-initialized at load, reset by rescal's last block every launch).
__global__ void build_kernel(const void* __restrict__ data) {
    __shared__ int s_is64;
    int tid = threadIdx.x;
    if (tid == 0) s_is64 = detect_is64(data);
    __syncthreads();
    int b = blockIdx.x * THREADS + tid;
    if (b < BATCH) {
        int r = read_idx(data, b * 5 + 2, s_is64, N_REL);
        int p = atomicAdd(&g_cnt[r], 1);
        g_list[r * BATCH + p] = b;
    }
}

struct __align__(16) Buf {
    float2 h[TILE][DIM];   // (h, ch)
    float2 t[TILE][DIM];   // (t, ct)
};

// Issue the async gather for one tile into one buffer (8 cp.async/thread).
__device__ __forceinline__ void issue_gather(
    Buf* buf, const int (*ids)[4], const float* __restrict__ ent, int tid)
{
    #pragma unroll
    for (int i = 0; i < 8; i++) {
        int flat = i * THREADS + tid;      // 0..4095
        int e = flat >> 9;                 // element 0..7
        int v = (flat >> 7) & 3;           // 0:h 1:t 2:ch 3:ct
        int k = flat & 127;
        const float* src = ent + (size_t)ids[e][v] * DIM + k;
        float2* base = (v == 0 || v == 2) ? &buf->h[e][k] : &buf->t[e][k];
        float*  dst  = (v == 0 || v == 1) ? &base->x : &base->y;
        cp4(dst, src);
    }
    cp_commit();
}

// Persistent: 296 blocks x 512 threads (2 blocks/SM -> 32 warps resident).
// Thread = (col = tid&127, row-quarter = tid>>7). R quarter-column in 32 regs.
// Double-buffered cp.async gather; packed f32x2 FMAs do pos+neg at once.
// Last-finishing block reduces per-block partials, stores out[0], and resets
// g_cnt / g_done so the next graph replay sees clean state.
__global__ __launch_bounds__(THREADS, 2) void rescal_kernel(
    const void*  __restrict__ data,
    const float* __restrict__ ent,
    const float* __restrict__ rel,
    float*       __restrict__ out)
{
    __shared__ Buf   s_buf[2];
    __shared__ int   s_toff[N_REL];
    __shared__ int   s_ws[8], s_winc[8];
    __shared__ int   s_nt, s_is64;
    __shared__ int   st_r[MAXT], st_s[MAXT], st_n[MAXT];
    __shared__ int   s_ids[MAXT][TILE][4];
    __shared__ float wsum[TILE][16];
    __shared__ float s_part4[4];
    __shared__ float s_red[16];
    __shared__ int   s_last;

    const int tid  = threadIdx.x;
    const int col  = tid & 127;
    const int rowq = tid >> 7;            // row quarter 0..3
    const int lane = tid & 31;
    const int wid  = tid >> 5;            // 0..15

    if (tid == 0) s_is64 = detect_is64(data);

    // ---- tile-offset scan over g_cnt (warps 0..7, shuffle scan) ----
    int tc = 0, incl = 0;
    if (tid < 256) {
        tc = (tid < N_REL) ? (g_cnt[tid] + TILE - 1) / TILE : 0;
        int v = tc;
        #pragma unroll
        for (int o = 1; o < 32; o <<= 1) {
            int u = __shfl_up_sync(0xffffffffu, v, o);
            if (lane >= o) v += u;
        }
        if (lane == 31) s_ws[wid] = v;
        incl = v;
    }
    __syncthreads();
    if (wid == 0) {
        int x = (lane < 8) ? s_ws[lane] : 0;
        #pragma unroll
        for (int o = 1; o < 8; o <<= 1) {
            int u = __shfl_up_sync(0xffffffffu, x, o);
            if (lane >= o) x += u;
        }
        if (lane < 8) s_winc[lane] = x;
    }
    __syncthreads();
    if (tid < 256) {
        int base = (wid == 0) ? 0 : s_winc[wid - 1];
        incl += base;
        if (tid < N_REL) s_toff[tid] = incl - tc;  // exclusive prefix
        if (tid == N_REL - 1) s_nt = incl;
    }
    __syncthreads();

    const int nt  = s_nt;
    const int t0  = (int)((long long)blockIdx.x * nt / NBLOCKS);
    const int t1  = (int)((long long)(blockIdx.x + 1) * nt / NBLOCKS);
    const int ntb = t1 - t0;
    const int is64 = s_is64;

    // ---- per-tile metadata: binary search for relation ----
    if (tid < ntb) {
        int t = t0 + tid;
        int lo = 0, hi = N_REL;
        while (hi - lo > 1) {
            int m = (lo + hi) >> 1;
            if (s_toff[m] <= t) lo = m; else hi = m;
        }
        int s0 = (t - s_toff[lo]) * TILE;
        int nv = g_cnt[lo] - s0;
        st_r[tid] = lo;
        st_s[tid] = s0;
        st_n[tid] = (nv > TILE) ? TILE : nv;
    }
    __syncthreads();

    // ---- prefetch all entity ids for this block's tiles ----
    if (tid < ntb * TILE) {
        int tt = tid >> 3, e = tid & 7;
        int nv = st_n[tt];
        int b  = g_list[st_r[tt] * BATCH + st_s[tt] + ((e < nv) ? e : 0)];
        s_ids[tt][e][0] = read_idx(data, b * 5 + 0, is64, N_ENT);  // h
        s_ids[tt][e][1] = read_idx(data, b * 5 + 1, is64, N_ENT);  // t
        s_ids[tt][e][2] = read_idx(data, b * 5 + 3, is64, N_ENT);  // ch
        s_ids[tt][e][3] = read_idx(data, b * 5 + 4, is64, N_ENT);  // ct
    }
    __syncthreads();

    float Rreg[32];
    int   cur_r = -1;
    float blockAcc = 0.0f;                 // carried on warps 0..3

    if (ntb > 0) issue_gather(&s_buf[0], s_ids[0], ent, tid);

    for (int j = 0; j < ntb; j++) {
        if (j + 1 < ntb)
            issue_gather(&s_buf[(j + 1) & 1], s_ids[j + 1], ent, tid);

        const int r = st_r[j];
        if (r != cur_r) {                  // reload R quarter-column (L2-hot)
            const float* Rp = rel + (size_t)r * (DIM * DIM)
                                  + (size_t)(rowq * 32) * DIM + col;
            #pragma unroll
            for (int k = 0; k < 32; k++) Rreg[k] = __ldg(Rp + (size_t)k * DIM);
            cur_r = r;
        }

        if (j + 1 < ntb) cp_wait1(); else cp_wait0();
        __syncthreads();                   // tile j's data visible to all

        const Buf* buf = &s_buf[j & 1];
        const int  nvalid = st_n[j];
        const int  kb = rowq * 32;

        ull acc[TILE];
        #pragma unroll
        for (int e = 0; e < TILE; e++) acc[e] = 0ull;

        #pragma unroll 4
        for (int k = 0; k < 32; k += 2) {
            ull b0 = dup2(Rreg[k]);
            ull b1 = dup2(Rreg[k + 1]);
            #pragma unroll
            for (int e = 0; e < TILE; e++) {
                ulonglong2 hv = *reinterpret_cast<const ulonglong2*>(&buf->h[e][kb + k]);
                acc[e] = ffma2(hv.x, b0, acc[e]);
                acc[e] = ffma2(hv.y, b1, acc[e]);
            }
        }

        // contrib_e = accp * t[col] - accn * ct[col]; per-warp reduce
        #pragma unroll
        for (int e = 0; e < TILE; e++) {
            ull tv = *reinterpret_cast<const ull*>(&buf->t[e][col]);
            ull p  = mul2(acc[e], tv);
            float c = __uint_as_float((unsigned int)p)
                    - __uint_as_float((unsigned int)(p >> 32));
            #pragma unroll
            for (int o = 16; o; o >>= 1)
                c += __shfl_xor_sync(0xffffffffu, c, o);
            if (lane == 0) wsum[e][wid] = c;
        }
        __syncthreads();                   // wsum ready; buf[(j+1)&1] free

        // Warps 0..3 combine: 16 lanes per element, e = wid*2 + (lane>>4).
        if (wid < 4) {
            int e = wid * 2 + (lane >> 4);
            int w = lane & 15;
            float v = wsum[e][w];
            v += __shfl_xor_sync(0xffffffffu, v, 8);
            v += __shfl_xor_sync(0xffffffffu, v, 4);
            v += __shfl_xor_sync(0xffffffffu, v, 2);
            v += __shfl_xor_sync(0xffffffffu, v, 1);
            if (w == 0 && e < nvalid) {
                v += 1.0f;                 // + MARGIN
                if (v > 0.0f) blockAcc += v * (1.0f / BATCH);
            }
        }
    }

    // ---- block partial + last-block completion ----
    if (wid < 4) {
        blockAcc += __shfl_xor_sync(0xffffffffu, blockAcc, 16);
        if (lane == 0) s_part4[wid] = blockAcc;
    }
    __syncthreads();
    if (tid == 0) {
        float total = s_part4[0] + s_part4[1] + s_part4[2] + s_part4[3];
        g_part[blockIdx.x] = total;
        __threadfence();
        unsigned int old = atomicAdd(&g_done, 1u);
        s_last = (old == NBLOCKS - 1) ? 1 : 0;
    }
    __syncthreads();
    if (s_last) {
        __threadfence();
        float v = (tid < NBLOCKS) ? g_part[tid] : 0.0f;
        #pragma unroll
        for (int o = 16; o; o >>= 1)
            v += __shfl_xor_sync(0xffffffffu, v, o);
        if (lane == 0) s_red[wid] = v;
        __syncthreads();
        if (wid == 0) {
            float x = (lane < 16) ? s_red[lane] : 0.0f;
            #pragma unroll
            for (int o = 8; o; o >>= 1)
                x += __shfl_xor_sync(0xffffffffu, x, o);
            if (lane == 0) out[0] = x;
        }
        // reset state for the next graph replay
        if (tid < N_REL) g_cnt[tid] = 0;
        if (tid == 0)    g_done = 0u;
    }
}

extern "C" void kernel_launch(void* const* d_in, const int* in_sizes, int n_in,
                              void* d_out, int out_size) {
    const void*  data = d_in[0];
    const float* ent  = (const float*)d_in[1];
    const float* rel  = (const float*)d_in[2];
    float*       out  = (float*)d_out;

    build_kernel<<<(BATCH + THREADS - 1) / THREADS, THREADS>>>(data);
    rescal_kernel<<<NBLOCKS, THREADS>>>(data, ent, rel, out);
}

// round 7
// speedup vs baseline: 1.3253x; 1.3253x over previous
#include <cuda_runtime.h>

#define N_REL   200
#define BATCH   16384
#define DIM     128
#define N_ENT   500000
#define TILE    4
#define NBLOCKS 296
#define THREADS 512
#define MAXT    24

// Scratch (static __device__ globals — no allocation allowed)
__device__ int          g_cnt[N_REL];          // zero at start; reset by last block
__device__ int          g_list[N_REL * BATCH];
__device__ float        g_part[NBLOCKS];
__device__ unsigned int g_done;                // zero-init; reset by last block

typedef unsigned long long ull;

// ---- packed f32x2 helpers (pos/neg bilinears share one issue slot) ----
__device__ __forceinline__ ull ffma2(ull a, ull b, ull c) {
    ull d;
    asm("fma.rn.f32x2 %0, %1, %2, %3;" : "=l"(d) : "l"(a), "l"(b), "l"(c));
    return d;
}
__device__ __forceinline__ ull mul2(ull a, ull b) {
    ull d;
    asm("mul.rn.f32x2 %0, %1, %2;" : "=l"(d) : "l"(a), "l"(b));
    return d;
}
__device__ __forceinline__ ull dup2(float x) {
    ull d; unsigned int xi = __float_as_uint(x);
    asm("mov.b64 %0, {%1, %2};" : "=l"(d) : "r"(xi), "r"(xi));
    return d;
}

// ---- cp.async helpers ----
__device__ __forceinline__ void cp4(void* dst, const void* src) {
    unsigned sa = (unsigned)__cvta_generic_to_shared(dst);
    asm volatile("cp.async.ca.shared.global [%0], [%1], 4;" :: "r"(sa), "l"(src));
}
__device__ __forceinline__ void cp_commit() {
    asm volatile("cp.async.commit_group;" ::: "memory");
}
__device__ __forceinline__ void cp_wait1() {
    asm volatile("cp.async.wait_group 1;" ::: "memory");
}
__device__ __forceinline__ void cp_wait0() {
    asm volatile("cp.async.wait_group 0;" ::: "memory");
}

// Detect int64-vs-int32 index dtype from first 32 elements.
__device__ __forceinline__ int detect_is64(const void* data) {
    const unsigned int* w = (const unsigned int*)data;
    unsigned int acc = 0;
    #pragma unroll
    for (int k = 0; k < 32; k++) acc |= w[2 * k + 1];
    return (acc == 0) ? 1 : 0;   // true int64 (<2^31) => odd words all zero
}

// Read data[elem] under either index dtype, with defensive clamping.
__device__ __forceinline__ int read_idx(const void* data, int elem, int is64, int limit) {
    long long v;
    if (is64) v = ((const long long*)data)[elem];
    else      v = ((const int*)data)[elem];
    if (v < 0) v = 0;
    if (v >= limit) v = limit - 1;
    return (int)v;
}

// Bucket batch elements by relation id (g_cnt zero on entry; reset each launch
// by rescal's last block).
__global__ void build_kernel(const void* __restrict__ data) {
    __shared__ int s_is64;
    int tid = threadIdx.x;
    if (tid == 0) s_is64 = detect_is64(data);
    __syncthreads();
    int b = blockIdx.x * THREADS + tid;
    if (b < BATCH) {
        int r = read_idx(data, b * 5 + 2, s_is64, N_REL);
        int p = atomicAdd(&g_cnt[r], 1);
        g_list[r * BATCH + p] = b;
    }
}

struct __align__(16) Buf {
    float2 h[TILE][DIM];   // (h, ch)
    float2 t[TILE][DIM];   // (t, ct)
};

// Async gather for one tile (2048 floats, 4 cp.async/thread).
__device__ __forceinline__ void issue_gather(
    Buf* buf, const int (*ids)[4], const float* __restrict__ ent, int tid)
{
    #pragma unroll
    for (int i = 0; i < 4; i++) {
        int flat = i * THREADS + tid;      // 0..2047
        int e = flat >> 9;                 // element 0..3
        int v = (flat >> 7) & 3;           // 0:h 1:t 2:ch 3:ct
        int k = flat & 127;
        const float* src = ent + (size_t)ids[e][v] * DIM + k;
        float2* base = (v == 0 || v == 2) ? &buf->h[e][k] : &buf->t[e][k];
        float*  dst  = (v == 0 || v == 1) ? &base->x : &base->y;
        cp4(dst, src);
    }
    cp_commit();
}

// Persistent: 296 blocks x 512 threads (2 blocks/SM -> 32 warps resident).
// Thread = (jpair = tid&63 -> columns 2jp,2jp+1 ; rowe = tid>>6 -> 16 k rows).
// R block (16k x 2j) in 32 regs; each 16B h-load feeds 4 packed FFMA2.
__global__ __launch_bounds__(THREADS, 2) void rescal_kernel(
    const void*  __restrict__ data,
    const float* __restrict__ ent,
    const float* __restrict__ rel,
    float*       __restrict__ out)
{
    __shared__ Buf   s_buf[2];
    __shared__ int   s_toff[N_REL];
    __shared__ int   s_ws[8], s_winc[8];
    __shared__ int   s_nt, s_is64;
    __shared__ int   st_r[MAXT], st_s[MAXT], st_n[MAXT];
    __shared__ int   s_ids[MAXT][TILE][4];
    __shared__ float wsum[TILE][16];
    __shared__ float s_part2[2];
    __shared__ float s_red[16];
    __shared__ int   s_last;

    const int tid  = threadIdx.x;
    const int jp   = tid & 63;            // column pair: j = 2jp, 2jp+1
    const int rowe = tid >> 6;            // row eighth: k in [rowe*16, +16)
    const int lane = tid & 31;
    const int wid  = tid >> 5;            // 0..15

    if (tid == 0) s_is64 = detect_is64(data);

    // ---- tile-offset scan over g_cnt (shuffle scan, warps 0..7) ----
    int tc = 0, incl = 0;
    if (tid < 256) {
        tc = (tid < N_REL) ? (g_cnt[tid] + TILE - 1) / TILE : 0;
        int v = tc;
        #pragma unroll
        for (int o = 1; o < 32; o <<= 1) {
            int u = __shfl_up_sync(0xffffffffu, v, o);
            if (lane >= o) v += u;
        }
        if (lane == 31) s_ws[wid] = v;
        incl = v;
    }
    __syncthreads();
    if (wid == 0) {
        int x = (lane < 8) ? s_ws[lane] : 0;
        #pragma unroll
        for (int o = 1; o < 8; o <<= 1) {
            int u = __shfl_up_sync(0xffffffffu, x, o);
            if (lane >= o) x += u;
        }
        if (lane < 8) s_winc[lane] = x;
    }
    __syncthreads();
    if (tid < 256) {
        int base = (wid == 0) ? 0 : s_winc[wid - 1];
        incl += base;
        if (tid < N_REL) s_toff[tid] = incl - tc;  // exclusive prefix
        if (tid == N_REL - 1) s_nt = incl;
    }
    __syncthreads();

    const int nt  = s_nt;
    const int t0  = (int)((long long)blockIdx.x * nt / NBLOCKS);
    const int t1  = (int)((long long)(blockIdx.x + 1) * nt / NBLOCKS);
    const int ntb = t1 - t0;
    const int is64 = s_is64;

    // ---- per-tile metadata: binary search for relation ----
    if (tid < ntb) {
        int t = t0 + tid;
        int lo = 0, hi = N_REL;
        while (hi - lo > 1) {
            int m = (lo + hi) >> 1;
            if (s_toff[m] <= t) lo = m; else hi = m;
        }
        int s0 = (t - s_toff[lo]) * TILE;
        int nv = g_cnt[lo] - s0;
        st_r[tid] = lo;
        st_s[tid] = s0;
        st_n[tid] = (nv > TILE) ? TILE : nv;
    }
    __syncthreads();

    // ---- prefetch all entity ids for this block's tiles ----
    if (tid < ntb * TILE) {
        int tt = tid >> 2, e = tid & 3;
        int nv = st_n[tt];
        int b  = g_list[st_r[tt] * BATCH + st_s[tt] + ((e < nv) ? e : 0)];
        s_ids[tt][e][0] = read_idx(data, b * 5 + 0, is64, N_ENT);  // h
        s_ids[tt][e][1] = read_idx(data, b * 5 + 1, is64, N_ENT);  // t
        s_ids[tt][e][2] = read_idx(data, b * 5 + 3, is64, N_ENT);  // ch
        s_ids[tt][e][3] = read_idx(data, b * 5 + 4, is64, N_ENT);  // ct
    }
    __syncthreads();

    float2 Rreg[16];                       // R[rowe*16+kk][2jp .. 2jp+1]
    int    cur_r = -1;
    float  blockAcc = 0.0f;                // carried on warps 0..1

    if (ntb > 0) issue_gather(&s_buf[0], s_ids[0], ent, tid);

    for (int j = 0; j < ntb; j++) {
        if (j + 1 < ntb)
            issue_gather(&s_buf[(j + 1) & 1], s_ids[j + 1], ent, tid);

        const int r = st_r[j];
        if (r != cur_r) {                  // reload R block (L2-hot, coalesced)
            const float* Rp = rel + (size_t)r * (DIM * DIM)
                                  + (size_t)(rowe * 16) * DIM + jp * 2;
            #pragma unroll
            for (int kk = 0; kk < 16; kk++)
                Rreg[kk] = __ldg((const float2*)(Rp + (size_t)kk * DIM));
            cur_r = r;
        }

        if (j + 1 < ntb) cp_wait1(); else cp_wait0();
        __syncthreads();                   // tile j's data visible

        const Buf* buf = &s_buf[j & 1];
        const int  nvalid = st_n[j];
        const int  kb = rowe * 16;

        ull acc0[TILE], acc1[TILE];        // (pos,neg) for j0 and j1
        #pragma unroll
        for (int e = 0; e < TILE; e++) { acc0[e] = 0ull; acc1[e] = 0ull; }

        #pragma unroll
        for (int kk = 0; kk < 16; kk += 2) {
            ull b00 = dup2(Rreg[kk].x);      // R[k][j0]
            ull b01 = dup2(Rreg[kk].y);      // R[k][j1]
            ull b10 = dup2(Rreg[kk + 1].x);  // R[k+1][j0]
            ull b11 = dup2(Rreg[kk + 1].y);  // R[k+1][j1]
            #pragma unroll
            for (int e = 0; e < TILE; e++) {
                ulonglong2 hv = *reinterpret_cast<const ulonglong2*>(&buf->h[e][kb + kk]);
                acc0[e] = ffma2(hv.x, b00, acc0[e]);
                acc1[e] = ffma2(hv.x, b01, acc1[e]);
                acc0[e] = ffma2(hv.y, b10, acc0[e]);
                acc1[e] = ffma2(hv.y, b11, acc1[e]);
            }
        }

        // contrib_e = sum_j accp*t[j] - accn*ct[j]; per-warp reduce (32 jp's)
        #pragma unroll
        for (int e = 0; e < TILE; e++) {
            ulonglong2 tv = *reinterpret_cast<const ulonglong2*>(&buf->t[e][jp * 2]);
            ull p = mul2(acc0[e], tv.x);
            ull q = mul2(acc1[e], tv.y);
            float c = (__uint_as_float((unsigned int)p)
                     - __uint_as_float((unsigned int)(p >> 32)))
                    + (__uint_as_float((unsigned int)q)
                     - __uint_as_float((unsigned int)(q >> 32)));
            #pragma unroll
            for (int o = 16; o; o >>= 1)
                c += __shfl_xor_sync(0xffffffffu, c, o);
            if (lane == 0) wsum[e][wid] = c;
        }
        __syncthreads();                   // wsum ready; buf[(j+1)&1] free

        // Warps 0..1 combine: 16 lanes per element, e = wid*2 + (lane>>4).
        if (wid < 2) {
            int e = wid * 2 + (lane >> 4);
            int w = lane & 15;
            float v = wsum[e][w];
            v += __shfl_xor_sync(0xffffffffu, v, 8);
            v += __shfl_xor_sync(0xffffffffu, v, 4);
            v += __shfl_xor_sync(0xffffffffu, v, 2);
            v += __shfl_xor_sync(0xffffffffu, v, 1);
            if (w == 0 && e < nvalid) {
                v += 1.0f;                 // + MARGIN
                if (v > 0.0f) blockAcc += v * (1.0f / BATCH);
            }
        }
    }

    // ---- block partial + last-block completion ----
    if (wid < 2) {
        blockAcc += __shfl_xor_sync(0xffffffffu, blockAcc, 16);
        if (lane == 0) s_part2[wid] = blockAcc;
    }
    __syncthreads();
    if (tid == 0) {
        float total = s_part2[0] + s_part2[1];
        g_part[blockIdx.x] = total;
        __threadfence();
        unsigned int old = atomicAdd(&g_done, 1u);
        s_last = (old == NBLOCKS - 1) ? 1 : 0;
    }
    __syncthreads();
    if (s_last) {
        __threadfence();
        float v = (tid < NBLOCKS) ? g_part[tid] : 0.0f;
        #pragma unroll
        for (int o = 16; o; o >>= 1)
            v += __shfl_xor_sync(0xffffffffu, v, o);
        if (lane == 0) s_red[wid] = v;
        __syncthreads();
        if (wid == 0) {
            float x = (lane < 16) ? s_red[lane] : 0.0f;
            #pragma unroll
            for (int o = 8; o; o >>= 1)
                x += __shfl_xor_sync(0xffffffffu, x, o);
            if (lane == 0) out[0] = x;
        }
        // reset state for next graph replay
        if (tid < N_REL) g_cnt[tid] = 0;
        if (tid == 0)    g_done = 0u;
    }
}

extern "C" void kernel_launch(void* const* d_in, const int* in_sizes, int n_in,
                              void* d_out, int out_size) {
    const void*  data = d_in[0];
    const float* ent  = (const float*)d_in[1];
    const float* rel  = (const float*)d_in[2];
    float*       out  = (float*)d_out;

    build_kernel<<<(BATCH + THREADS - 1) / THREADS, THREADS>>>(data);
    rescal_kernel<<<NBLOCKS, THREADS>>>(data, ent, rel, out);
}